// round 1
// baseline (speedup 1.0000x reference)
#include <cuda_runtime.h>
#include <cstdint>

// Problem constants
#define NB 4
#define NC 256
#define NPIX 4096          // 64*64
#define NDQ 32             // D = C/8

// ---------------- device scratch (no allocations allowed) ----------------
__device__ float g_qT[NB * NPIX * NDQ];    // [b][n][d]
__device__ float g_kT[NB * NPIX * NDQ];    // [b][n][d]
__device__ float g_vT[(size_t)NB * NPIX * NC];  // [b][n][c]

// ---------------- packed fp32x2 helpers (Blackwell FFMA2) ----------------
__device__ __forceinline__ void fma2_acc(unsigned long long& d,
                                         unsigned long long a,
                                         unsigned long long b) {
    asm("fma.rn.f32x2 %0, %1, %2, %0;" : "+l"(d) : "l"(a), "l"(b));
}
__device__ __forceinline__ unsigned long long pack2(float x) {
    unsigned long long r;
    asm("mov.b64 %0, {%1, %1};" : "=l"(r) : "f"(x));
    return r;
}
__device__ __forceinline__ void unpack2(unsigned long long v, float& lo, float& hi) {
    asm("mov.b64 {%0, %1}, %2;" : "=f"(lo), "=f"(hi) : "l"(v));
}

// ---------------- kernel 1: 1x1-conv projection GEMM ----------------
// Y[m][n] = sum_c W[m][c] * x[b][c][n] + bias[m], written TRANSPOSED:
//   dst[b][n][m]  (M = 32 for q/k, 256 for v)
// Tile: TM=32 (rows of W), TN=64 (pixels), TK=32. 256 threads, 2x4 micro-tile.
__global__ void __launch_bounds__(256)
proj_kernel(const float* __restrict__ x, const float* __restrict__ W,
            const float* __restrict__ bias, float* __restrict__ dst, int M)
{
    const int b  = blockIdx.z;
    const int m0 = blockIdx.y * 32;
    const int n0 = blockIdx.x * 64;
    const int tid = threadIdx.x;
    const int tm = tid >> 4;      // 0..15
    const int tn = tid & 15;      // 0..15

    __shared__ float Ws[32][33];
    __shared__ float Xs[32][65];

    float acc[2][4] = {{0.f,0.f,0.f,0.f},{0.f,0.f,0.f,0.f}};

    for (int k0 = 0; k0 < NC; k0 += 32) {
        // W tile: 32x32
        #pragma unroll
        for (int it = 0; it < 4; ++it) {
            int idx = tid + it * 256;
            int r = idx >> 5, c = idx & 31;
            Ws[r][c] = W[(size_t)(m0 + r) * NC + k0 + c];
        }
        // X tile: 32x64
        #pragma unroll
        for (int it = 0; it < 8; ++it) {
            int idx = tid + it * 256;
            int r = idx >> 6, c = idx & 63;
            Xs[r][c] = x[((size_t)b * NC + k0 + r) * NPIX + n0 + c];
        }
        __syncthreads();
        #pragma unroll
        for (int kt = 0; kt < 32; ++kt) {
            float a0 = Ws[2 * tm + 0][kt];
            float a1 = Ws[2 * tm + 1][kt];
            #pragma unroll
            for (int c = 0; c < 4; ++c) {
                float bb = Xs[kt][4 * tn + c];
                acc[0][c] += a0 * bb;
                acc[1][c] += a1 * bb;
            }
        }
        __syncthreads();
    }

    #pragma unroll
    for (int r = 0; r < 2; ++r) {
        float bi = bias[m0 + 2 * tm + r];
        #pragma unroll
        for (int c = 0; c < 4; ++c) {
            dst[((size_t)b * NPIX + n0 + 4 * tn + c) * (size_t)M + m0 + 2 * tm + r]
                = acc[r][c] + bi;
        }
    }
}

// ---------------- kernel 2: fused attention ----------------
// Per CTA: 32 query rows (one batch). 256 threads = 8 warps.
// Warp g owns output channels [g*32, g*32+32); lane = query row.
// No-max softmax (logits are tiny): O[i][c] = sum_j exp(S[i][j]) * V[j][c],
// l[i] = sum_j exp(S[i][j]); out = gamma*O/l + x.
__global__ void __launch_bounds__(256)
attn_kernel(const float* __restrict__ x, const float* __restrict__ gamma,
            float* __restrict__ out)
{
    const int b    = blockIdx.y;
    const int n0   = blockIdx.x * 32;
    const int tid  = threadIdx.x;
    const int g    = tid >> 5;    // warp id: channel group
    const int lane = tid & 31;    // query row within tile

    __shared__ float4 Ks4[32][8];     // [key j][d4]      4 KB
    __shared__ float4 Vs4[32][64];    // [key j][c4]     32 KB
    __shared__ float  Ps[32][33];     // [query i][key j] padded
    __shared__ float  lred[8][32];

    // Q row for this lane -> registers
    float4 q4[8];
    {
        const float4* qp = reinterpret_cast<const float4*>(
            g_qT + ((size_t)b * NPIX + n0 + lane) * NDQ);
        #pragma unroll
        for (int d = 0; d < 8; ++d) q4[d] = qp[d];
    }

    unsigned long long Oc[16];   // 16 packed f32x2 accumulators = 32 channels
    #pragma unroll
    for (int i = 0; i < 16; ++i) Oc[i] = 0ull;   // bit pattern of (0.f, 0.f)
    float lpart = 0.f;

    const float4* kbase = reinterpret_cast<const float4*>(g_kT + (size_t)b * NPIX * NDQ);
    const float4* vbase = reinterpret_cast<const float4*>(g_vT + (size_t)b * NPIX * NC);

    for (int k0 = 0; k0 < NPIX; k0 += 32) {
        __syncthreads();   // previous PV done before overwriting tiles
        // K tile: 256 float4, one per thread
        {
            int j = tid >> 3, d = tid & 7;
            Ks4[j][d] = kbase[(size_t)(k0 + j) * 8 + d];
        }
        // V tile: 2048 float4, 8 per thread
        #pragma unroll
        for (int it = 0; it < 8; ++it) {
            int idx = tid + it * 256;
            int j = idx >> 6, c = idx & 63;
            Vs4[j][c] = vbase[(size_t)(k0 + j) * 64 + c];
        }
        __syncthreads();

        // S[i][j] for j = g*4 .. g*4+3  (K reads are warp-broadcast)
        float acc0 = 0.f, acc1 = 0.f, acc2 = 0.f, acc3 = 0.f;
        #pragma unroll
        for (int d = 0; d < 8; ++d) {
            float4 qv = q4[d];
            float4 k0v = Ks4[g * 4 + 0][d];
            float4 k1v = Ks4[g * 4 + 1][d];
            float4 k2v = Ks4[g * 4 + 2][d];
            float4 k3v = Ks4[g * 4 + 3][d];
            acc0 += qv.x * k0v.x + qv.y * k0v.y + qv.z * k0v.z + qv.w * k0v.w;
            acc1 += qv.x * k1v.x + qv.y * k1v.y + qv.z * k1v.z + qv.w * k1v.w;
            acc2 += qv.x * k2v.x + qv.y * k2v.y + qv.z * k2v.z + qv.w * k2v.w;
            acc3 += qv.x * k3v.x + qv.y * k3v.y + qv.z * k3v.z + qv.w * k3v.w;
        }
        float p0 = __expf(acc0), p1 = __expf(acc1),
              p2 = __expf(acc2), p3 = __expf(acc3);
        Ps[lane][g * 4 + 0] = p0;
        Ps[lane][g * 4 + 1] = p1;
        Ps[lane][g * 4 + 2] = p2;
        Ps[lane][g * 4 + 3] = p3;
        lpart += (p0 + p1) + (p2 + p3);
        __syncthreads();

        // PV: O[lane][g*32 + 0..31] += P[lane][j] * V[j][...]
        // V reads are identical across the warp -> LDS.64 broadcast.
        #pragma unroll 4
        for (int j = 0; j < 32; ++j) {
            float pj = Ps[lane][j];
            unsigned long long pp = pack2(pj);
            const unsigned long long* vr =
                reinterpret_cast<const unsigned long long*>(&Vs4[j][g * 8]);
            #pragma unroll
            for (int cc = 0; cc < 16; ++cc)
                fma2_acc(Oc[cc], pp, vr[cc]);
        }
    }

    // reduce l over the 8 warps
    lred[g][lane] = lpart;
    __syncthreads();
    float l = 0.f;
    #pragma unroll
    for (int gg = 0; gg < 8; ++gg) l += lred[gg][lane];

    const float inv = gamma[0] / l;
    const size_t base = ((size_t)b * NC + g * 32) * NPIX + n0 + lane;
    #pragma unroll
    for (int cc = 0; cc < 16; ++cc) {
        float lo, hi;
        unpack2(Oc[cc], lo, hi);
        size_t i0 = base + (size_t)(2 * cc) * NPIX;
        size_t i1 = base + (size_t)(2 * cc + 1) * NPIX;
        out[i0] = lo * inv + x[i0];
        out[i1] = hi * inv + x[i1];
    }
}

// ---------------- launch ----------------
extern "C" void kernel_launch(void* const* d_in, const int* in_sizes, int n_in,
                              void* d_out, int out_size)
{
    (void)in_sizes; (void)n_in; (void)out_size;
    const float* x     = (const float*)d_in[0];
    const float* Wq    = (const float*)d_in[1];
    const float* bq    = (const float*)d_in[2];
    const float* Wk    = (const float*)d_in[3];
    const float* bk    = (const float*)d_in[4];
    const float* Wv    = (const float*)d_in[5];
    const float* bv    = (const float*)d_in[6];
    const float* gamma = (const float*)d_in[7];
    float* out = (float*)d_out;

    void* p;
    cudaGetSymbolAddress(&p, g_qT); float* qT = (float*)p;
    cudaGetSymbolAddress(&p, g_kT); float* kT = (float*)p;
    cudaGetSymbolAddress(&p, g_vT); float* vT = (float*)p;

    proj_kernel<<<dim3(NPIX / 64, 1, NB), 256>>>(x, Wq, bq, qT, NDQ);
    proj_kernel<<<dim3(NPIX / 64, 1, NB), 256>>>(x, Wk, bk, kT, NDQ);
    proj_kernel<<<dim3(NPIX / 64, NC / 32, NB), 256>>>(x, Wv, bv, vT, NC);

    attn_kernel<<<dim3(NPIX / 32, NB), 256>>>(x, gamma, out);
}

// round 2
// speedup vs baseline: 1.3613x; 1.3613x over previous
#include <cuda_runtime.h>
#include <cstdint>

// Problem constants
#define NB 4
#define NC 256
#define NPIX 4096          // 64*64
#define NDQ 32             // D = C/8

// ---------------- device scratch (no allocations allowed) ----------------
__device__ float g_qT[NB * NPIX * NDQ];    // [b][n][d]
__device__ float g_kT[NB * NPIX * NDQ];    // [b][n][d]
__device__ float g_vT[(size_t)NB * NPIX * NC];  // [b][n][c]

// ---------------- packed fp32x2 helpers (Blackwell FFMA2) ----------------
__device__ __forceinline__ void fma2_acc(unsigned long long& d,
                                         unsigned long long a,
                                         unsigned long long b) {
    asm("fma.rn.f32x2 %0, %1, %2, %0;" : "+l"(d) : "l"(a), "l"(b));
}
__device__ __forceinline__ unsigned long long pack2(float x) {
    unsigned long long r;
    asm("mov.b64 %0, {%1, %1};" : "=l"(r) : "f"(x));
    return r;
}
__device__ __forceinline__ void unpack2(unsigned long long v, float& lo, float& hi) {
    asm("mov.b64 {%0, %1}, %2;" : "=f"(lo), "=f"(hi) : "l"(v));
}

// ---------------- kernel 1: 1x1-conv projection GEMM ----------------
// dst[b][n][m] = sum_c W[m][c] * x[b][c][n] + bias[m]
__global__ void __launch_bounds__(256)
proj_kernel(const float* __restrict__ x, const float* __restrict__ W,
            const float* __restrict__ bias, float* __restrict__ dst, int M)
{
    const int b  = blockIdx.z;
    const int m0 = blockIdx.y * 32;
    const int n0 = blockIdx.x * 64;
    const int tid = threadIdx.x;
    const int tm = tid >> 4;      // 0..15
    const int tn = tid & 15;      // 0..15

    __shared__ float Ws[32][33];
    __shared__ float Xs[32][65];

    float acc[2][4] = {{0.f,0.f,0.f,0.f},{0.f,0.f,0.f,0.f}};

    for (int k0 = 0; k0 < NC; k0 += 32) {
        #pragma unroll
        for (int it = 0; it < 4; ++it) {
            int idx = tid + it * 256;
            int r = idx >> 5, c = idx & 31;
            Ws[r][c] = W[(size_t)(m0 + r) * NC + k0 + c];
        }
        #pragma unroll
        for (int it = 0; it < 8; ++it) {
            int idx = tid + it * 256;
            int r = idx >> 6, c = idx & 63;
            Xs[r][c] = x[((size_t)b * NC + k0 + r) * NPIX + n0 + c];
        }
        __syncthreads();
        #pragma unroll
        for (int kt = 0; kt < 32; ++kt) {
            float a0 = Ws[2 * tm + 0][kt];
            float a1 = Ws[2 * tm + 1][kt];
            #pragma unroll
            for (int c = 0; c < 4; ++c) {
                float bb = Xs[kt][4 * tn + c];
                acc[0][c] += a0 * bb;
                acc[1][c] += a1 * bb;
            }
        }
        __syncthreads();
    }

    #pragma unroll
    for (int r = 0; r < 2; ++r) {
        float bi = bias[m0 + 2 * tm + r];
        #pragma unroll
        for (int c = 0; c < 4; ++c) {
            dst[((size_t)b * NPIX + n0 + 4 * tn + c) * (size_t)M + m0 + 2 * tm + r]
                = acc[r][c] + bi;
        }
    }
}

// ---------------- kernel 2: fused attention ----------------
// Per CTA: 64 query rows (one batch). 256 threads = 8 warps.
// Warp g owns output channels [g*32, g*32+32).
// Each lane handles TWO query rows: (lane) and (lane+32)  -> V-register reuse.
// No-max softmax (logits are tiny, |S|<~5): O[i][c] = sum_j exp(S[i][j])*V[j][c].
__global__ void __launch_bounds__(256, 1)
attn_kernel(const float* __restrict__ x, const float* __restrict__ gamma,
            float* __restrict__ out)
{
    const int b    = blockIdx.y;
    const int n0   = blockIdx.x * 64;
    const int tid  = threadIdx.x;
    const int g    = tid >> 5;    // warp id: channel group
    const int lane = tid & 31;

    __shared__ unsigned long long Ks2[32][16];  // [key j][d-pair]   4 KB
    __shared__ float4 Vs4[32][64];              // [key j][c4]      32 KB
    __shared__ float  Ps[64][33];               // [query i][key j]  8.25 KB
    __shared__ float  lred[8][64];              //                   2 KB

    // Two Q rows for this lane -> registers, packed as f32x2 over d
    unsigned long long q2[2][16];
    {
        const unsigned long long* qp0 = reinterpret_cast<const unsigned long long*>(
            g_qT + ((size_t)b * NPIX + n0 + lane) * NDQ);
        const unsigned long long* qp1 = reinterpret_cast<const unsigned long long*>(
            g_qT + ((size_t)b * NPIX + n0 + 32 + lane) * NDQ);
        #pragma unroll
        for (int d = 0; d < 16; ++d) { q2[0][d] = qp0[d]; q2[1][d] = qp1[d]; }
    }

    unsigned long long Oc0[16], Oc1[16];  // 2 queries x 32 channels (f32x2 pairs)
    #pragma unroll
    for (int i = 0; i < 16; ++i) { Oc0[i] = 0ull; Oc1[i] = 0ull; }
    float lp0 = 0.f, lp1 = 0.f;

    const float4* kbase = reinterpret_cast<const float4*>(g_kT + (size_t)b * NPIX * NDQ);
    const float4* vbase = reinterpret_cast<const float4*>(g_vT + (size_t)b * NPIX * NC);

    for (int k0 = 0; k0 < NPIX; k0 += 32) {
        __syncthreads();   // previous PV done before overwriting tiles
        // K tile: 32 keys x 32 d = 256 float4, one per thread
        {
            int j = tid >> 3, d = tid & 7;
            reinterpret_cast<float4*>(&Ks2[j][0])[d] = kbase[(size_t)(k0 + j) * 8 + d];
        }
        // V tile: 2048 float4, 8 per thread
        #pragma unroll
        for (int it = 0; it < 8; ++it) {
            int idx = tid + it * 256;
            int j = idx >> 6, c = idx & 63;
            Vs4[j][c] = vbase[(size_t)(k0 + j) * 64 + c];
        }
        __syncthreads();

        // QK: warp g computes keys g*4..g*4+3 for both of its queries (f32x2)
        unsigned long long s2[2][4];
        #pragma unroll
        for (int qi = 0; qi < 2; ++qi)
            #pragma unroll
            for (int kk = 0; kk < 4; ++kk) s2[qi][kk] = 0ull;
        #pragma unroll
        for (int d = 0; d < 16; ++d) {
            unsigned long long kv0 = Ks2[g * 4 + 0][d];
            unsigned long long kv1 = Ks2[g * 4 + 1][d];
            unsigned long long kv2 = Ks2[g * 4 + 2][d];
            unsigned long long kv3 = Ks2[g * 4 + 3][d];
            fma2_acc(s2[0][0], q2[0][d], kv0);
            fma2_acc(s2[0][1], q2[0][d], kv1);
            fma2_acc(s2[0][2], q2[0][d], kv2);
            fma2_acc(s2[0][3], q2[0][d], kv3);
            fma2_acc(s2[1][0], q2[1][d], kv0);
            fma2_acc(s2[1][1], q2[1][d], kv1);
            fma2_acc(s2[1][2], q2[1][d], kv2);
            fma2_acc(s2[1][3], q2[1][d], kv3);
        }
        #pragma unroll
        for (int qi = 0; qi < 2; ++qi) {
            #pragma unroll
            for (int kk = 0; kk < 4; ++kk) {
                float lo, hi;
                unpack2(s2[qi][kk], lo, hi);
                float p = __expf(lo + hi);
                Ps[qi * 32 + lane][g * 4 + kk] = p;
                if (qi == 0) lp0 += p; else lp1 += p;
            }
        }
        __syncthreads();

        // PV: each V register feeds BOTH queries (2 FFMA2 per LDS.64)
        #pragma unroll 4
        for (int j = 0; j < 32; ++j) {
            unsigned long long pp0 = pack2(Ps[lane][j]);
            unsigned long long pp1 = pack2(Ps[32 + lane][j]);
            const unsigned long long* vr =
                reinterpret_cast<const unsigned long long*>(&Vs4[j][g * 8]);
            #pragma unroll
            for (int cc = 0; cc < 16; ++cc) {
                unsigned long long vv = vr[cc];
                fma2_acc(Oc0[cc], pp0, vv);
                fma2_acc(Oc1[cc], pp1, vv);
            }
        }
    }

    // reduce l over the 8 warps
    lred[g][lane] = lp0;
    lred[g][32 + lane] = lp1;
    __syncthreads();
    float l0 = 0.f, l1 = 0.f;
    #pragma unroll
    for (int gg = 0; gg < 8; ++gg) { l0 += lred[gg][lane]; l1 += lred[gg][32 + lane]; }

    const float gma = gamma[0];
    const float inv0 = gma / l0;
    const float inv1 = gma / l1;
    const size_t base0 = ((size_t)b * NC + g * 32) * NPIX + n0 + lane;
    const size_t base1 = base0 + 32;
    #pragma unroll
    for (int cc = 0; cc < 16; ++cc) {
        float lo, hi;
        unpack2(Oc0[cc], lo, hi);
        size_t i0 = base0 + (size_t)(2 * cc) * NPIX;
        size_t i1 = base0 + (size_t)(2 * cc + 1) * NPIX;
        out[i0] = lo * inv0 + x[i0];
        out[i1] = hi * inv0 + x[i1];
        unpack2(Oc1[cc], lo, hi);
        i0 = base1 + (size_t)(2 * cc) * NPIX;
        i1 = base1 + (size_t)(2 * cc + 1) * NPIX;
        out[i0] = lo * inv1 + x[i0];
        out[i1] = hi * inv1 + x[i1];
    }
}

// ---------------- launch ----------------
extern "C" void kernel_launch(void* const* d_in, const int* in_sizes, int n_in,
                              void* d_out, int out_size)
{
    (void)in_sizes; (void)n_in; (void)out_size;
    const float* x     = (const float*)d_in[0];
    const float* Wq    = (const float*)d_in[1];
    const float* bq    = (const float*)d_in[2];
    const float* Wk    = (const float*)d_in[3];
    const float* bk    = (const float*)d_in[4];
    const float* Wv    = (const float*)d_in[5];
    const float* bv    = (const float*)d_in[6];
    const float* gamma = (const float*)d_in[7];
    float* out = (float*)d_out;

    void* p;
    cudaGetSymbolAddress(&p, g_qT); float* qT = (float*)p;
    cudaGetSymbolAddress(&p, g_kT); float* kT = (float*)p;
    cudaGetSymbolAddress(&p, g_vT); float* vT = (float*)p;

    proj_kernel<<<dim3(NPIX / 64, 1, NB), 256>>>(x, Wq, bq, qT, NDQ);
    proj_kernel<<<dim3(NPIX / 64, 1, NB), 256>>>(x, Wk, bk, kT, NDQ);
    proj_kernel<<<dim3(NPIX / 64, NC / 32, NB), 256>>>(x, Wv, bv, vT, NC);

    attn_kernel<<<dim3(NPIX / 64, NB), 256>>>(x, gamma, out);
}

// round 4
// speedup vs baseline: 4.8463x; 3.5601x over previous
#include <cuda_runtime.h>
#include <cuda_bf16.h>
#include <cstdint>

#define NB 4
#define NC 256
#define NPIX 4096
#define ND 32

// ---------------- device scratch ----------------
__device__ __align__(256) __nv_bfloat16 g_q[(size_t)NB * NPIX * ND];   // [b][n][d]
__device__ __align__(256) __nv_bfloat16 g_k[(size_t)NB * NPIX * ND];   // [b][n][d]
__device__ __align__(256) __nv_bfloat16 g_v[(size_t)NB * NPIX * NC];   // [b][n][c]

// ---------------- PTX helpers ----------------
__device__ __forceinline__ uint32_t smem_u32(const void* p) {
    uint32_t a;
    asm("{ .reg .u64 t; cvta.to.shared.u64 t, %1; cvt.u32.u64 %0, t; }" : "=r"(a) : "l"(p));
    return a;
}
__device__ __forceinline__ void cp16(uint32_t dst, const void* src) {
    asm volatile("cp.async.cg.shared.global [%0], [%1], 16;" :: "r"(dst), "l"(src));
}
#define CP_COMMIT() asm volatile("cp.async.commit_group;" ::: "memory")
#define CP_WAIT1()  asm volatile("cp.async.wait_group 1;" ::: "memory")
#define CP_WAIT0()  asm volatile("cp.async.wait_group 0;" ::: "memory")

__device__ __forceinline__ void ldsm4(uint32_t r[4], uint32_t addr) {
    asm volatile("ldmatrix.sync.aligned.m8n8.x4.shared.b16 {%0,%1,%2,%3}, [%4];"
        : "=r"(r[0]), "=r"(r[1]), "=r"(r[2]), "=r"(r[3]) : "r"(addr));
}
__device__ __forceinline__ void ldsm4t(uint32_t r[4], uint32_t addr) {
    asm volatile("ldmatrix.sync.aligned.m8n8.x4.trans.shared.b16 {%0,%1,%2,%3}, [%4];"
        : "=r"(r[0]), "=r"(r[1]), "=r"(r[2]), "=r"(r[3]) : "r"(addr));
}
__device__ __forceinline__ void mma16816(float c[4], const uint32_t a[4],
                                         uint32_t b0, uint32_t b1) {
    asm volatile(
        "mma.sync.aligned.m16n8k16.row.col.f32.bf16.bf16.f32 "
        "{%0,%1,%2,%3}, {%4,%5,%6,%7}, {%8,%9}, {%0,%1,%2,%3};"
        : "+f"(c[0]), "+f"(c[1]), "+f"(c[2]), "+f"(c[3])
        : "r"(a[0]), "r"(a[1]), "r"(a[2]), "r"(a[3]), "r"(b0), "r"(b1));
}
__device__ __forceinline__ uint32_t packbf(float lo, float hi) {
    uint32_t r;
    asm("cvt.rn.satfinite.bf16x2.f32 %0, %1, %2;" : "=r"(r) : "f"(hi), "f"(lo));
    return r;
}

// ---------------- kernel 1a: q/k projection -> bf16 [b][n][32] ----------------
__global__ void __launch_bounds__(256)
proj_qk(const float* __restrict__ x, const float* __restrict__ W,
        const float* __restrict__ bias, __nv_bfloat16* __restrict__ dst)
{
    const int b  = blockIdx.z;
    const int n0 = blockIdx.x * 64;
    const int tid = threadIdx.x;
    const int tm = tid >> 4, tn = tid & 15;

    __shared__ float Ws[32][33];
    __shared__ float Xs[32][65];
    float acc[2][4] = {{0.f,0.f,0.f,0.f},{0.f,0.f,0.f,0.f}};

    for (int k0 = 0; k0 < NC; k0 += 32) {
        #pragma unroll
        for (int it = 0; it < 4; ++it) {
            int idx = tid + it * 256; int r = idx >> 5, c = idx & 31;
            Ws[r][c] = W[(size_t)r * NC + k0 + c];
        }
        #pragma unroll
        for (int it = 0; it < 8; ++it) {
            int idx = tid + it * 256; int r = idx >> 6, c = idx & 63;
            Xs[r][c] = x[((size_t)b * NC + k0 + r) * NPIX + n0 + c];
        }
        __syncthreads();
        #pragma unroll
        for (int kt = 0; kt < 32; ++kt) {
            float a0 = Ws[2 * tm + 0][kt], a1 = Ws[2 * tm + 1][kt];
            #pragma unroll
            for (int c = 0; c < 4; ++c) {
                float bb = Xs[kt][4 * tn + c];
                acc[0][c] += a0 * bb; acc[1][c] += a1 * bb;
            }
        }
        __syncthreads();
    }
    #pragma unroll
    for (int r = 0; r < 2; ++r) {
        int m = 2 * tm + r;
        float bi = bias[m];
        #pragma unroll
        for (int c = 0; c < 4; ++c)
            dst[((size_t)b * NPIX + n0 + 4 * tn + c) * ND + m] =
                __float2bfloat16(acc[r][c] + bi);
    }
}

// ---------------- kernel 1b: v projection -> bf16 [b][n][c] ----------------
__global__ void __launch_bounds__(256)
proj_v(const float* __restrict__ x, const float* __restrict__ W,
       const float* __restrict__ bias, __nv_bfloat16* __restrict__ dst)
{
    const int b  = blockIdx.z;
    const int m0 = blockIdx.y * 32;
    const int n0 = blockIdx.x * 64;
    const int tid = threadIdx.x;
    const int tm = tid >> 4, tn = tid & 15;

    __shared__ float Ws[32][33];
    __shared__ float Xs[32][65];
    float acc[2][4] = {{0.f,0.f,0.f,0.f},{0.f,0.f,0.f,0.f}};

    for (int k0 = 0; k0 < NC; k0 += 32) {
        #pragma unroll
        for (int it = 0; it < 4; ++it) {
            int idx = tid + it * 256; int r = idx >> 5, c = idx & 31;
            Ws[r][c] = W[(size_t)(m0 + r) * NC + k0 + c];
        }
        #pragma unroll
        for (int it = 0; it < 8; ++it) {
            int idx = tid + it * 256; int r = idx >> 6, c = idx & 63;
            Xs[r][c] = x[((size_t)b * NC + k0 + r) * NPIX + n0 + c];
        }
        __syncthreads();
        #pragma unroll
        for (int kt = 0; kt < 32; ++kt) {
            float a0 = Ws[2 * tm + 0][kt], a1 = Ws[2 * tm + 1][kt];
            #pragma unroll
            for (int c = 0; c < 4; ++c) {
                float bb = Xs[kt][4 * tn + c];
                acc[0][c] += a0 * bb; acc[1][c] += a1 * bb;
            }
        }
        __syncthreads();
    }
    #pragma unroll
    for (int r = 0; r < 2; ++r) {
        int m = m0 + 2 * tm + r;
        float bi = bias[m];
        #pragma unroll
        for (int c = 0; c < 4; ++c)
            dst[((size_t)b * NPIX + n0 + 4 * tn + c) * NC + m] =
                __float2bfloat16(acc[r][c] + bi);
    }
}

// ---------------- kernel 2: HMMA flash attention ----------------
// CTA: 64 queries of one batch, 256 threads = 8 warps.
//   warp w: qb = w>>1 (16 query rows), ch = w&1 (128 output channels).
// Key tile = 64 keys, cp.async double-buffered.
// SMEM (dynamic): padded strides for conflict-free ldmatrix.
#define KSTRIDE 80        // 64B data + 16B pad
#define VSTRIDE 528       // 512B data + 16B pad
#define SQ  0
#define SK0 (SQ  + 64 * KSTRIDE)
#define SK1 (SK0 + 64 * KSTRIDE)
#define SV0 (SK1 + 64 * KSTRIDE)
#define SV1 (SV0 + 64 * VSTRIDE)
#define SM_TOTAL (SV1 + 64 * VSTRIDE)

__global__ void __launch_bounds__(256, 1)
attn_kernel(const float* __restrict__ x, const float* __restrict__ gamma,
            float* __restrict__ out)
{
    extern __shared__ char smem[];
    const uint32_t sb = smem_u32(smem);
    const int b   = blockIdx.y;
    const int n0q = blockIdx.x * 64;
    const int tid = threadIdx.x;
    const int w = tid >> 5, lane = tid & 31;
    const int qb = w >> 1;          // query block (16 rows)
    const int ch = w & 1;           // channel half (128 chans)
    const int grp = lane >> 3, rr = lane & 7;
    const int gr = lane >> 2, lc = lane & 3;

    const __nv_bfloat16* qg = g_q + ((size_t)b * NPIX + n0q) * ND;
    const __nv_bfloat16* kg = g_k + (size_t)b * NPIX * ND;
    const __nv_bfloat16* vg = g_v + (size_t)b * NPIX * NC;

    // ---- prologue: Q + tile 0 ----
    {   // Q: 64 rows x 64B -> 256 cp16
        int r = tid >> 2, c = tid & 3;
        cp16(sb + SQ + (uint32_t)r * KSTRIDE + c * 16, qg + (size_t)r * ND + c * 8);
        cp16(sb + SK0 + (uint32_t)r * KSTRIDE + c * 16, kg + (size_t)r * ND + c * 8);
    }
    #pragma unroll
    for (int it = 0; it < 8; ++it) {   // V: 64 rows x 512B -> 2048 cp16
        int idx = tid + it * 256;
        int r = idx >> 5, c = idx & 31;
        cp16(sb + SV0 + (uint32_t)r * VSTRIDE + c * 16, vg + (size_t)r * NC + c * 8);
    }
    CP_COMMIT();

    float Oacc[16][4];
    #pragma unroll
    for (int i = 0; i < 16; ++i)
        #pragma unroll
        for (int j = 0; j < 4; ++j) Oacc[i][j] = 0.f;
    float l_lo = 0.f, l_hi = 0.f;
    uint32_t qf[2][4];

    for (int t = 0; t < 64; ++t) {
        __syncthreads();   // previous compute done before its buffer is overwritten
        const uint32_t kbuf = sb + ((t & 1) ? SK1 : SK0);
        const uint32_t vbuf = sb + ((t & 1) ? SV1 : SV0);
        if (t < 63) {
            const uint32_t kbufN = sb + ((t & 1) ? SK0 : SK1);
            const uint32_t vbufN = sb + ((t & 1) ? SV0 : SV1);
            const int k0n = (t + 1) * 64;
            {
                int r = tid >> 2, c = tid & 3;
                cp16(kbufN + (uint32_t)r * KSTRIDE + c * 16,
                     kg + (size_t)(k0n + r) * ND + c * 8);
            }
            #pragma unroll
            for (int it = 0; it < 8; ++it) {
                int idx = tid + it * 256;
                int r = idx >> 5, c = idx & 31;
                cp16(vbufN + (uint32_t)r * VSTRIDE + c * 16,
                     vg + (size_t)(k0n + r) * NC + c * 8);
            }
            CP_COMMIT();
            CP_WAIT1();
        } else {
            CP_WAIT0();
        }
        __syncthreads();   // tile t visible

        if (t == 0) {      // Q A-fragments (once)
            #pragma unroll
            for (int ks = 0; ks < 2; ++ks) {
                uint32_t addr = sb + SQ
                    + (uint32_t)(qb * 16 + (grp & 1) * 8 + rr) * KSTRIDE
                    + ks * 32 + (grp >> 1) * 16;
                ldsm4(qf[ks], addr);
            }
        }

        // ---- S = Q * K^T : 8 n8-tiles (keys), 2 k16 steps ----
        float sacc[8][4];
        #pragma unroll
        for (int i = 0; i < 8; ++i)
            #pragma unroll
            for (int j = 0; j < 4; ++j) sacc[i][j] = 0.f;
        #pragma unroll
        for (int ks = 0; ks < 2; ++ks) {
            #pragma unroll
            for (int p = 0; p < 4; ++p) {
                uint32_t bfr[4];
                uint32_t addr = kbuf
                    + (uint32_t)(p * 16 + (grp >> 1) * 8 + rr) * KSTRIDE
                    + ks * 32 + (grp & 1) * 16;
                ldsm4(bfr, addr);
                mma16816(sacc[2 * p],     qf[ks], bfr[0], bfr[1]);
                mma16816(sacc[2 * p + 1], qf[ks], bfr[2], bfr[3]);
            }
        }

        // ---- exp, row-sum, pack P into A-fragments ----
        uint32_t pf[4][4];
        #pragma unroll
        for (int nt = 0; nt < 8; ++nt) {
            float e0 = __expf(sacc[nt][0]);
            float e1 = __expf(sacc[nt][1]);
            float e2 = __expf(sacc[nt][2]);
            float e3 = __expf(sacc[nt][3]);
            l_lo += e0 + e1;
            l_hi += e2 + e3;
            int kb = nt >> 1;
            if ((nt & 1) == 0) {
                pf[kb][0] = packbf(e0, e1);
                pf[kb][1] = packbf(e2, e3);
            } else {
                pf[kb][2] = packbf(e0, e1);
                pf[kb][3] = packbf(e2, e3);
            }
        }

        // ---- O += P * V : 16 n8-tiles (channels), 4 k16 steps ----
        #pragma unroll
        for (int kb = 0; kb < 4; ++kb) {
            #pragma unroll
            for (int np = 0; np < 8; ++np) {
                uint32_t bfr[4];
                uint32_t addr = vbuf
                    + (uint32_t)(kb * 16 + (grp & 1) * 8 + rr) * VSTRIDE
                    + ch * 256 + np * 32 + (grp >> 1) * 16;
                ldsm4t(bfr, addr);
                mma16816(Oacc[2 * np],     pf[kb], bfr[0], bfr[1]);
                mma16816(Oacc[2 * np + 1], pf[kb], bfr[2], bfr[3]);
            }
        }
    }

    // ---- reduce l across the quad (lanes sharing the same row) ----
    l_lo += __shfl_xor_sync(0xFFFFFFFF, l_lo, 1);
    l_lo += __shfl_xor_sync(0xFFFFFFFF, l_lo, 2);
    l_hi += __shfl_xor_sync(0xFFFFFFFF, l_hi, 1);
    l_hi += __shfl_xor_sync(0xFFFFFFFF, l_hi, 2);
    const float gma = gamma[0];
    const float inv_lo = gma / l_lo;
    const float inv_hi = gma / l_hi;

    // ---- epilogue: out = gamma*O/l + x ----
    const int pix0 = n0q + qb * 16 + gr;
    #pragma unroll
    for (int nt = 0; nt < 16; ++nt) {
        int c0 = ch * 128 + nt * 8 + 2 * lc;
        size_t i00 = ((size_t)b * NC + c0) * NPIX + pix0;
        size_t i01 = i00 + NPIX;           // channel c0+1
        out[i00] = Oacc[nt][0] * inv_lo + x[i00];
        out[i01] = Oacc[nt][1] * inv_lo + x[i01];
        size_t i10 = i00 + 8;              // row +8
        size_t i11 = i01 + 8;
        out[i10] = Oacc[nt][2] * inv_hi + x[i10];
        out[i11] = Oacc[nt][3] * inv_hi + x[i11];
    }
}

// ---------------- launch ----------------
extern "C" void kernel_launch(void* const* d_in, const int* in_sizes, int n_in,
                              void* d_out, int out_size)
{
    (void)in_sizes; (void)n_in; (void)out_size;
    const float* x     = (const float*)d_in[0];
    const float* Wq    = (const float*)d_in[1];
    const float* bq    = (const float*)d_in[2];
    const float* Wk    = (const float*)d_in[3];
    const float* bk    = (const float*)d_in[4];
    const float* Wv    = (const float*)d_in[5];
    const float* bv    = (const float*)d_in[6];
    const float* gamma = (const float*)d_in[7];
    float* out = (float*)d_out;

    void* p;
    cudaGetSymbolAddress(&p, g_q); __nv_bfloat16* qT = (__nv_bfloat16*)p;
    cudaGetSymbolAddress(&p, g_k); __nv_bfloat16* kT = (__nv_bfloat16*)p;
    cudaGetSymbolAddress(&p, g_v); __nv_bfloat16* vT = (__nv_bfloat16*)p;

    static int smem_set = 0;
    if (!smem_set) {
        cudaFuncSetAttribute(attn_kernel,
                             cudaFuncAttributeMaxDynamicSharedMemorySize, SM_TOTAL);
        smem_set = 1;
    }

    proj_qk<<<dim3(NPIX / 64, 1, NB), 256>>>(x, Wq, bq, qT);
    proj_qk<<<dim3(NPIX / 64, 1, NB), 256>>>(x, Wk, bk, kT);
    proj_v <<<dim3(NPIX / 64, NC / 32, NB), 256>>>(x, Wv, bv, vT);

    attn_kernel<<<dim3(NPIX / 64, NB), 256, SM_TOTAL>>>(x, gamma, out);
}

// round 5
// speedup vs baseline: 8.4057x; 1.7345x over previous
#include <cuda_runtime.h>
#include <cuda_bf16.h>
#include <cstdint>

#define NB 4
#define NC 256
#define NPIX 4096
#define ND 32

// ---------------- device scratch ----------------
__device__ __align__(256) __nv_bfloat16 g_q[(size_t)NB * NPIX * ND];   // [b][n][d]
__device__ __align__(256) __nv_bfloat16 g_k[(size_t)NB * NPIX * ND];   // [b][n][d]
__device__ __align__(256) __nv_bfloat16 g_v[(size_t)NB * NPIX * NC];   // [b][n][c]
__device__ __align__(256) __nv_bfloat16 g_xbf[(size_t)NB * NC * NPIX]; // [b][c][n]
__device__ __align__(256) __nv_bfloat16 g_wall[320 * NC];              // q(32),k(32),v(256) rows
__device__ __align__(256) float         g_ball[320];

// ---------------- PTX helpers ----------------
__device__ __forceinline__ uint32_t smem_u32(const void* p) {
    uint32_t a;
    asm("{ .reg .u64 t; cvta.to.shared.u64 t, %1; cvt.u32.u64 %0, t; }" : "=r"(a) : "l"(p));
    return a;
}
__device__ __forceinline__ void cp16(uint32_t dst, const void* src) {
    asm volatile("cp.async.cg.shared.global [%0], [%1], 16;" :: "r"(dst), "l"(src));
}
#define CP_COMMIT() asm volatile("cp.async.commit_group;" ::: "memory")
#define CP_WAIT1()  asm volatile("cp.async.wait_group 1;" ::: "memory")
#define CP_WAIT0()  asm volatile("cp.async.wait_group 0;" ::: "memory")

__device__ __forceinline__ void ldsm4(uint32_t r[4], uint32_t addr) {
    asm volatile("ldmatrix.sync.aligned.m8n8.x4.shared.b16 {%0,%1,%2,%3}, [%4];"
        : "=r"(r[0]), "=r"(r[1]), "=r"(r[2]), "=r"(r[3]) : "r"(addr));
}
__device__ __forceinline__ void ldsm4t(uint32_t r[4], uint32_t addr) {
    asm volatile("ldmatrix.sync.aligned.m8n8.x4.trans.shared.b16 {%0,%1,%2,%3}, [%4];"
        : "=r"(r[0]), "=r"(r[1]), "=r"(r[2]), "=r"(r[3]) : "r"(addr));
}
__device__ __forceinline__ void mma16816(float c[4], const uint32_t a[4],
                                         uint32_t b0, uint32_t b1) {
    asm volatile(
        "mma.sync.aligned.m16n8k16.row.col.f32.bf16.bf16.f32 "
        "{%0,%1,%2,%3}, {%4,%5,%6,%7}, {%8,%9}, {%0,%1,%2,%3};"
        : "+f"(c[0]), "+f"(c[1]), "+f"(c[2]), "+f"(c[3])
        : "r"(a[0]), "r"(a[1]), "r"(a[2]), "r"(a[3]), "r"(b0), "r"(b1));
}
__device__ __forceinline__ uint32_t packbf(float lo, float hi) {
    uint32_t r;
    asm("cvt.rn.satfinite.bf16x2.f32 %0, %1, %2;" : "=r"(r) : "f"(hi), "f"(lo));
    return r;
}

// ---------------- kernel 0a: x -> bf16 ----------------
__global__ void __launch_bounds__(256)
xconvert(const float* __restrict__ x, __nv_bfloat16* __restrict__ xbf)
{
    size_t i4 = (size_t)blockIdx.x * 256 + threadIdx.x;   // float4 index
    float4 v = reinterpret_cast<const float4*>(x)[i4];
    uint2 o;
    o.x = packbf(v.x, v.y);
    o.y = packbf(v.z, v.w);
    reinterpret_cast<uint2*>(xbf)[i4] = o;
}

// ---------------- kernel 0b: pack Wq/Wk/Wv + biases ----------------
__global__ void __launch_bounds__(256)
packw(const float* __restrict__ Wq, const float* __restrict__ bq,
      const float* __restrict__ Wk, const float* __restrict__ bk,
      const float* __restrict__ Wv, const float* __restrict__ bv,
      __nv_bfloat16* __restrict__ wall, float* __restrict__ ball)
{
    int r = blockIdx.x;            // 0..319
    int c = threadIdx.x;           // 0..255
    float wv, bvl;
    if (r < 32)       { wv = Wq[(size_t)r * NC + c];        bvl = bq[r]; }
    else if (r < 64)  { wv = Wk[(size_t)(r - 32) * NC + c]; bvl = bk[r - 32]; }
    else              { wv = Wv[(size_t)(r - 64) * NC + c]; bvl = bv[r - 64]; }
    wall[(size_t)r * NC + c] = __float2bfloat16(wv);
    if (c == 0) ball[r] = bvl;
}

// ---------------- kernel 1: fused HMMA projection ----------------
// Per CTA: 64 pixels of one batch. GEMM M=64 (pixels), N=320 (q|k|v), K=256.
// A from g_xbf [c][n] via ldmatrix.trans; B from g_wall [n][k] via ldmatrix.
// 8 warps = 4 m16 blocks x 2 n-halves (160 cols each).
#define XSTR 144                        // 64 bf16 + 16B pad
#define WSTR 528                        // 256 bf16 + 16B pad
#define PSM_X 0
#define PSM_W (256 * XSTR)              // 36864
#define PSM_TOTAL (PSM_W + 320 * WSTR)  // 205824

__global__ void __launch_bounds__(256, 1)
proj_fused(const __nv_bfloat16* __restrict__ xbf,
           const __nv_bfloat16* __restrict__ wall,
           const float* __restrict__ ball,
           __nv_bfloat16* __restrict__ q,
           __nv_bfloat16* __restrict__ k,
           __nv_bfloat16* __restrict__ v)
{
    extern __shared__ char smem[];
    const uint32_t sb = smem_u32(smem);
    const int b   = blockIdx.y;
    const int n0  = blockIdx.x * 64;
    const int tid = threadIdx.x;
    const int w = tid >> 5, lane = tid & 31;
    const int m0  = (w >> 1) * 16;       // pixel block
    const int ncb = (w & 1) * 160;       // output-column half
    const int grp = lane >> 3, rr = lane & 7;
    const int gr = lane >> 2, lc = lane & 3;

    // ---- load A (x slice, [c=256][n=64]) and B (wall, [320][256]) ----
    #pragma unroll
    for (int it = 0; it < 8; ++it) {
        int idx = tid + it * 256;        // 2048 cp16
        int r = idx >> 3, c = idx & 7;
        cp16(sb + PSM_X + (uint32_t)r * XSTR + c * 16,
             xbf + ((size_t)b * NC + r) * NPIX + n0 + c * 8);
    }
    #pragma unroll
    for (int it = 0; it < 40; ++it) {
        int idx = tid + it * 256;        // 10240 cp16
        int r = idx >> 5, c = idx & 31;
        cp16(sb + PSM_W + (uint32_t)r * WSTR + c * 16,
             wall + (size_t)r * NC + c * 8);
    }
    CP_COMMIT();
    CP_WAIT0();
    __syncthreads();

    float acc[20][4];
    #pragma unroll
    for (int j = 0; j < 20; ++j)
        #pragma unroll
        for (int i = 0; i < 4; ++i) acc[j][i] = 0.f;

    // ---- K loop: 16 k16 steps ----
    #pragma unroll 4
    for (int ks = 0; ks < 16; ++ks) {
        uint32_t af[4];
        // A (m16k16) from [k][m] storage: trans load
        ldsm4t(af, sb + PSM_X
                   + (uint32_t)(ks * 16 + (grp >> 1) * 8 + rr) * XSTR
                   + (m0 + (grp & 1) * 8) * 2);
        #pragma unroll
        for (int j = 0; j < 10; ++j) {
            uint32_t bfr[4];
            // B (n16k16) from [n][k] storage: non-trans load
            ldsm4(bfr, sb + PSM_W
                       + (uint32_t)(ncb + j * 16 + (grp >> 1) * 8 + rr) * WSTR
                       + ks * 32 + (grp & 1) * 16);
            mma16816(acc[2 * j],     af, bfr[0], bfr[1]);
            mma16816(acc[2 * j + 1], af, bfr[2], bfr[3]);
        }
    }

    // ---- epilogue: add bias, pack bf16 pairs, route to q/k/v ----
    const int row0 = n0 + m0 + gr;
    #pragma unroll
    for (int j = 0; j < 20; ++j) {
        int col = ncb + j * 8 + 2 * lc;
        float b0 = ball[col], b1 = ball[col + 1];
        uint32_t lop = packbf(acc[j][0] + b0, acc[j][1] + b1);
        uint32_t hip = packbf(acc[j][2] + b0, acc[j][3] + b1);
        uint32_t* dst;
        int cc;
        if (col < 32)      { dst = reinterpret_cast<uint32_t*>(q); cc = col; 
                             size_t r0 = ((size_t)b * NPIX + row0) * ND + cc;
                             dst[r0 >> 1] = lop;
                             dst[(r0 + 8 * ND) >> 1] = hip; }
        else if (col < 64) { dst = reinterpret_cast<uint32_t*>(k); cc = col - 32;
                             size_t r0 = ((size_t)b * NPIX + row0) * ND + cc;
                             dst[r0 >> 1] = lop;
                             dst[(r0 + 8 * ND) >> 1] = hip; }
        else               { dst = reinterpret_cast<uint32_t*>(v); cc = col - 64;
                             size_t r0 = ((size_t)b * NPIX + row0) * NC + cc;
                             dst[r0 >> 1] = lop;
                             dst[(r0 + 8 * NC) >> 1] = hip; }
    }
}

// ---------------- kernel 2: HMMA flash attention (unchanged from R4) ----------------
#define KSTRIDE 80
#define VSTRIDE 528
#define SQ  0
#define SK0 (SQ  + 64 * KSTRIDE)
#define SK1 (SK0 + 64 * KSTRIDE)
#define SV0 (SK1 + 64 * KSTRIDE)
#define SV1 (SV0 + 64 * VSTRIDE)
#define SM_TOTAL (SV1 + 64 * VSTRIDE)

__global__ void __launch_bounds__(256, 1)
attn_kernel(const float* __restrict__ x, const float* __restrict__ gamma,
            float* __restrict__ out)
{
    extern __shared__ char smem[];
    const uint32_t sb = smem_u32(smem);
    const int b   = blockIdx.y;
    const int n0q = blockIdx.x * 64;
    const int tid = threadIdx.x;
    const int w = tid >> 5, lane = tid & 31;
    const int qb = w >> 1;
    const int ch = w & 1;
    const int grp = lane >> 3, rr = lane & 7;
    const int gr = lane >> 2, lc = lane & 3;

    const __nv_bfloat16* qg = g_q + ((size_t)b * NPIX + n0q) * ND;
    const __nv_bfloat16* kg = g_k + (size_t)b * NPIX * ND;
    const __nv_bfloat16* vg = g_v + (size_t)b * NPIX * NC;

    {
        int r = tid >> 2, c = tid & 3;
        cp16(sb + SQ + (uint32_t)r * KSTRIDE + c * 16, qg + (size_t)r * ND + c * 8);
        cp16(sb + SK0 + (uint32_t)r * KSTRIDE + c * 16, kg + (size_t)r * ND + c * 8);
    }
    #pragma unroll
    for (int it = 0; it < 8; ++it) {
        int idx = tid + it * 256;
        int r = idx >> 5, c = idx & 31;
        cp16(sb + SV0 + (uint32_t)r * VSTRIDE + c * 16, vg + (size_t)r * NC + c * 8);
    }
    CP_COMMIT();

    float Oacc[16][4];
    #pragma unroll
    for (int i = 0; i < 16; ++i)
        #pragma unroll
        for (int j = 0; j < 4; ++j) Oacc[i][j] = 0.f;
    float l_lo = 0.f, l_hi = 0.f;
    uint32_t qf[2][4];

    for (int t = 0; t < 64; ++t) {
        __syncthreads();
        const uint32_t kbuf = sb + ((t & 1) ? SK1 : SK0);
        const uint32_t vbuf = sb + ((t & 1) ? SV1 : SV0);
        if (t < 63) {
            const uint32_t kbufN = sb + ((t & 1) ? SK0 : SK1);
            const uint32_t vbufN = sb + ((t & 1) ? SV0 : SV1);
            const int k0n = (t + 1) * 64;
            {
                int r = tid >> 2, c = tid & 3;
                cp16(kbufN + (uint32_t)r * KSTRIDE + c * 16,
                     kg + (size_t)(k0n + r) * ND + c * 8);
            }
            #pragma unroll
            for (int it = 0; it < 8; ++it) {
                int idx = tid + it * 256;
                int r = idx >> 5, c = idx & 31;
                cp16(vbufN + (uint32_t)r * VSTRIDE + c * 16,
                     vg + (size_t)(k0n + r) * NC + c * 8);
            }
            CP_COMMIT();
            CP_WAIT1();
        } else {
            CP_WAIT0();
        }
        __syncthreads();

        if (t == 0) {
            #pragma unroll
            for (int ks = 0; ks < 2; ++ks) {
                uint32_t addr = sb + SQ
                    + (uint32_t)(qb * 16 + (grp & 1) * 8 + rr) * KSTRIDE
                    + ks * 32 + (grp >> 1) * 16;
                ldsm4(qf[ks], addr);
            }
        }

        float sacc[8][4];
        #pragma unroll
        for (int i = 0; i < 8; ++i)
            #pragma unroll
            for (int j = 0; j < 4; ++j) sacc[i][j] = 0.f;
        #pragma unroll
        for (int ks = 0; ks < 2; ++ks) {
            #pragma unroll
            for (int p = 0; p < 4; ++p) {
                uint32_t bfr[4];
                uint32_t addr = kbuf
                    + (uint32_t)(p * 16 + (grp >> 1) * 8 + rr) * KSTRIDE
                    + ks * 32 + (grp & 1) * 16;
                ldsm4(bfr, addr);
                mma16816(sacc[2 * p],     qf[ks], bfr[0], bfr[1]);
                mma16816(sacc[2 * p + 1], qf[ks], bfr[2], bfr[3]);
            }
        }

        uint32_t pf[4][4];
        #pragma unroll
        for (int nt = 0; nt < 8; ++nt) {
            float e0 = __expf(sacc[nt][0]);
            float e1 = __expf(sacc[nt][1]);
            float e2 = __expf(sacc[nt][2]);
            float e3 = __expf(sacc[nt][3]);
            l_lo += e0 + e1;
            l_hi += e2 + e3;
            int kb = nt >> 1;
            if ((nt & 1) == 0) {
                pf[kb][0] = packbf(e0, e1);
                pf[kb][1] = packbf(e2, e3);
            } else {
                pf[kb][2] = packbf(e0, e1);
                pf[kb][3] = packbf(e2, e3);
            }
        }

        #pragma unroll
        for (int kb = 0; kb < 4; ++kb) {
            #pragma unroll
            for (int np = 0; np < 8; ++np) {
                uint32_t bfr[4];
                uint32_t addr = vbuf
                    + (uint32_t)(kb * 16 + (grp & 1) * 8 + rr) * VSTRIDE
                    + ch * 256 + np * 32 + (grp >> 1) * 16;
                ldsm4t(bfr, addr);
                mma16816(Oacc[2 * np],     pf[kb], bfr[0], bfr[1]);
                mma16816(Oacc[2 * np + 1], pf[kb], bfr[2], bfr[3]);
            }
        }
    }

    l_lo += __shfl_xor_sync(0xFFFFFFFF, l_lo, 1);
    l_lo += __shfl_xor_sync(0xFFFFFFFF, l_lo, 2);
    l_hi += __shfl_xor_sync(0xFFFFFFFF, l_hi, 1);
    l_hi += __shfl_xor_sync(0xFFFFFFFF, l_hi, 2);
    const float gma = gamma[0];
    const float inv_lo = gma / l_lo;
    const float inv_hi = gma / l_hi;

    const int pix0 = n0q + qb * 16 + gr;
    #pragma unroll
    for (int nt = 0; nt < 16; ++nt) {
        int c0 = ch * 128 + nt * 8 + 2 * lc;
        size_t i00 = ((size_t)b * NC + c0) * NPIX + pix0;
        size_t i01 = i00 + NPIX;
        out[i00] = Oacc[nt][0] * inv_lo + x[i00];
        out[i01] = Oacc[nt][1] * inv_lo + x[i01];
        size_t i10 = i00 + 8;
        size_t i11 = i01 + 8;
        out[i10] = Oacc[nt][2] * inv_hi + x[i10];
        out[i11] = Oacc[nt][3] * inv_hi + x[i11];
    }
}

// ---------------- launch ----------------
extern "C" void kernel_launch(void* const* d_in, const int* in_sizes, int n_in,
                              void* d_out, int out_size)
{
    (void)in_sizes; (void)n_in; (void)out_size;
    const float* x     = (const float*)d_in[0];
    const float* Wq    = (const float*)d_in[1];
    const float* bq    = (const float*)d_in[2];
    const float* Wk    = (const float*)d_in[3];
    const float* bk    = (const float*)d_in[4];
    const float* Wv    = (const float*)d_in[5];
    const float* bv    = (const float*)d_in[6];
    const float* gamma = (const float*)d_in[7];
    float* out = (float*)d_out;

    void* p;
    cudaGetSymbolAddress(&p, g_q);    __nv_bfloat16* qT  = (__nv_bfloat16*)p;
    cudaGetSymbolAddress(&p, g_k);    __nv_bfloat16* kT  = (__nv_bfloat16*)p;
    cudaGetSymbolAddress(&p, g_v);    __nv_bfloat16* vT  = (__nv_bfloat16*)p;
    cudaGetSymbolAddress(&p, g_xbf);  __nv_bfloat16* xbf = (__nv_bfloat16*)p;
    cudaGetSymbolAddress(&p, g_wall); __nv_bfloat16* wal = (__nv_bfloat16*)p;
    cudaGetSymbolAddress(&p, g_ball); float*         bal = (float*)p;

    static int attr_set = 0;
    if (!attr_set) {
        cudaFuncSetAttribute(attn_kernel,
                             cudaFuncAttributeMaxDynamicSharedMemorySize, SM_TOTAL);
        cudaFuncSetAttribute(proj_fused,
                             cudaFuncAttributeMaxDynamicSharedMemorySize, PSM_TOTAL);
        attr_set = 1;
    }

    xconvert<<<(NB * NC * NPIX) / (256 * 4), 256>>>(x, xbf);
    packw<<<320, 256>>>(Wq, bq, Wk, bk, Wv, bv, wal, bal);
    proj_fused<<<dim3(NPIX / 64, NB), 256, PSM_TOTAL>>>(xbf, wal, bal, qT, kT, vT);
    attn_kernel<<<dim3(NPIX / 64, NB), 256, SM_TOTAL>>>(x, gamma, out);
}